// round 1
// baseline (speedup 1.0000x reference)
#include <cuda_runtime.h>
#include <cuda_bf16.h>
#include <math.h>

// ---------------------------------------------------------------------------
// Problem constants
//   N=2048, T=128, IN=64, H=256, 3H=768, NH=2, HD=128, C=30
// ---------------------------------------------------------------------------

#define NB    2048
#define TT    128
#define INDIM 64
#define HH    256
#define G3    768
#define NHD   2
#define HD    128
#define CC    30
#define NTROWS (NB * TT)   // 262144

// ---------------------------------------------------------------------------
// Device scratch (allocation-free rule: __device__ globals)
// ---------------------------------------------------------------------------
__device__ float g_xw[(size_t)NTROWS * G3];   // 805 MB: xW for current layer
__device__ float g_ys0[(size_t)NTROWS * HH];  // 268 MB: layer-0 outputs
__device__ float g_gates[NB * G3];            // per-step h @ Whh^T + bhh
__device__ float g_h[NB * HH];                // hidden state
__device__ float g_qh1[NHD * CC * HD];
__device__ float g_kh1[NHD * NB * HD];
__device__ float g_vh1[NHD * NB * HD];
__device__ float g_B[CC * NHD * HD];          // (30, 256)
__device__ float g_qh2[NHD * NB * HD];
__device__ float g_kh2[NHD * CC * HD];
__device__ float g_vh2[NHD * CC * HD];
__device__ float g_Sp[NB * HH];
__device__ float g_Smix[NB * HH];
__device__ float g_mlp[NB * HH];
__device__ float g_yraw[NB];

// ---------------------------------------------------------------------------
// Tiled GEMM: C[M,Nn] = A[M,K] @ W[Nn,K]^T + bias[Nn]
// Requires M%64==0, Nn%64==0, K%16==0. Block (16,16), 64x64 tile, BK=16,
// each thread computes a 4x4 fragment from transposed SMEM tiles (float4,
// conflict-free compute reads).
// ---------------------------------------------------------------------------
__global__ __launch_bounds__(256) void gemm_bias_kernel(
    const float* __restrict__ A, int lda,
    const float* __restrict__ W,
    const float* __restrict__ bias,
    float* __restrict__ C, int ldc,
    int M, int Nn, int K)
{
    __shared__ float As[16][64];
    __shared__ float Ws[16][64];
    const int tx = threadIdx.x, ty = threadIdx.y;
    const int tid = ty * 16 + tx;
    const int row0 = blockIdx.y * 64;
    const int col0 = blockIdx.x * 64;
    const int lm = tid >> 2;          // 0..63
    const int lk = (tid & 3) << 2;    // 0,4,8,12
    const float* Aptr = A + (size_t)(row0 + lm) * lda + lk;
    const float* Wptr = W + (size_t)(col0 + lm) * K + lk;

    float acc[4][4];
#pragma unroll
    for (int i = 0; i < 4; i++)
#pragma unroll
        for (int j = 0; j < 4; j++) acc[i][j] = 0.f;

    for (int k0 = 0; k0 < K; k0 += 16) {
        float4 av = *(const float4*)(Aptr + k0);
        float4 wv = *(const float4*)(Wptr + k0);
        As[lk + 0][lm] = av.x; As[lk + 1][lm] = av.y;
        As[lk + 2][lm] = av.z; As[lk + 3][lm] = av.w;
        Ws[lk + 0][lm] = wv.x; Ws[lk + 1][lm] = wv.y;
        Ws[lk + 2][lm] = wv.z; Ws[lk + 3][lm] = wv.w;
        __syncthreads();
#pragma unroll
        for (int k = 0; k < 16; k++) {
            float4 a = *(const float4*)(&As[k][ty << 2]);
            float4 b = *(const float4*)(&Ws[k][tx << 2]);
            float ar[4] = {a.x, a.y, a.z, a.w};
            float br[4] = {b.x, b.y, b.z, b.w};
#pragma unroll
            for (int i = 0; i < 4; i++)
#pragma unroll
                for (int j = 0; j < 4; j++) acc[i][j] += ar[i] * br[j];
        }
        __syncthreads();
    }
#pragma unroll
    for (int i = 0; i < 4; i++) {
        const int r = row0 + (ty << 2) + i;
        float* Crow = C + (size_t)r * ldc + col0 + (tx << 2);
#pragma unroll
        for (int j = 0; j < 4; j++)
            Crow[j] = acc[i][j] + bias[col0 + (tx << 2) + j];
    }
}

// ---------------------------------------------------------------------------
// GRU gate update: reads xW slice (row stride ldxw) + gates (h@Whh^T+bhh),
// updates h in place, optionally stores h to ys (layer-0 sequence buffer).
// ---------------------------------------------------------------------------
__global__ void gru_gate_kernel(const float* __restrict__ xw, size_t ldxw,
                                const float* __restrict__ g,
                                float* __restrict__ h,
                                float* __restrict__ ys, size_t ldys)
{
    const int idx = blockIdx.x * blockDim.x + threadIdx.x;  // 0..NB*HH-1
    const int n = idx >> 8;
    const int j = idx & 255;
    const float* xr = xw + (size_t)n * ldxw;
    const float* gr = g + (size_t)n * G3;
    const float r  = 1.f / (1.f + expf(-(xr[j] + gr[j])));
    const float z  = 1.f / (1.f + expf(-(xr[HH + j] + gr[HH + j])));
    const float nn = tanhf(xr[2 * HH + j] + r * gr[2 * HH + j]);
    const float hn = (1.f - z) * nn + z * h[idx];
    h[idx] = hn;
    if (ys) ys[(size_t)n * ldys + j] = hn;
}

// ---------------------------------------------------------------------------
// Per-head projection: out[n,row,col] = sum_d A[row,d] * Wm[n,d,col] + bias[n,col]
// A is [M,256], Wm is (NH,256,128), out (NH,M,128). grid (8, ceil(M/16), NH).
// ---------------------------------------------------------------------------
__global__ void proj_kernel(const float* __restrict__ A, int M,
                            const float* __restrict__ Wm,
                            const float* __restrict__ bias,
                            float* __restrict__ out)
{
    const int head = blockIdx.z;
    const int col = blockIdx.x * 16 + threadIdx.x;
    const int row = blockIdx.y * 16 + threadIdx.y;
    const int rc = min(row, M - 1);
    const float* W = Wm + (size_t)head * HH * HD;
    __shared__ float As[16][17], Ws[16][17];
    float acc = 0.f;
    for (int k0 = 0; k0 < HH; k0 += 16) {
        As[threadIdx.y][threadIdx.x] = A[(size_t)rc * HH + k0 + threadIdx.x];
        Ws[threadIdx.y][threadIdx.x] = W[(size_t)(k0 + threadIdx.y) * HD + col];
        __syncthreads();
#pragma unroll
        for (int k = 0; k < 16; k++)
            acc += As[threadIdx.y][k] * Ws[k][threadIdx.x];
        __syncthreads();
    }
    if (row < M)
        out[((size_t)head * M + row) * HD + col] = acc + bias[head * HD + col];
}

// ---------------------------------------------------------------------------
// MHA1: B = attn(R, S, S). One block per (head, l in 30). 256 threads.
// Softmax over 2048 keys; output written as B[l, head*128+h].
// ---------------------------------------------------------------------------
__global__ void attn1_kernel(const float* __restrict__ qh,
                             const float* __restrict__ kh,
                             const float* __restrict__ vh,
                             float* __restrict__ B)
{
    const int head = blockIdx.x / CC;
    const int l = blockIdx.x % CC;
    const int tid = threadIdx.x;
    __shared__ float p[NB];
    __shared__ float q[HD];
    __shared__ float red[256];
    if (tid < HD) q[tid] = qh[((size_t)head * CC + l) * HD + tid];
    __syncthreads();
    const float scale = 0.08838834764831845f;  // 1/sqrt(128)
    float lmax = -1e30f;
    for (int k = tid; k < NB; k += 256) {
        const float* kr = kh + ((size_t)head * NB + k) * HD;
        float s = 0.f;
#pragma unroll 4
        for (int d = 0; d < HD; d++) s += q[d] * kr[d];
        s *= scale;
        p[k] = s;
        lmax = fmaxf(lmax, s);
    }
    red[tid] = lmax; __syncthreads();
    for (int s = 128; s > 0; s >>= 1) {
        if (tid < s) red[tid] = fmaxf(red[tid], red[tid + s]);
        __syncthreads();
    }
    const float m = red[0];
    __syncthreads();
    float lsum = 0.f;
    for (int k = tid; k < NB; k += 256) {
        const float e = expf(p[k] - m);
        p[k] = e;
        lsum += e;
    }
    red[tid] = lsum; __syncthreads();
    for (int s = 128; s > 0; s >>= 1) {
        if (tid < s) red[tid] += red[tid + s];
        __syncthreads();
    }
    const float inv = 1.f / red[0];
    __syncthreads();
    const int col = tid & 127;
    const int half = tid >> 7;
    float o = 0.f;
    for (int k = half * 1024; k < half * 1024 + 1024; k++)
        o += p[k] * vh[((size_t)head * NB + k) * HD + col];
    red[tid] = o; __syncthreads();
    if (tid < HD)
        B[l * (NHD * HD) + head * HD + tid] = (red[tid] + red[tid + 128]) * inv;
}

// ---------------------------------------------------------------------------
// MHA2: S' = attn(S, B, B). One block per (l in 2048, head). 128 threads.
// Only 30 keys -> softmax recomputed per thread (cheap).
// ---------------------------------------------------------------------------
__global__ void attn2_kernel(const float* __restrict__ qh,
                             const float* __restrict__ kh,
                             const float* __restrict__ vh,
                             float* __restrict__ Sp)
{
    const int l = blockIdx.x;
    const int head = blockIdx.y;
    const int tid = threadIdx.x;  // 0..127
    __shared__ float q[HD];
    __shared__ float sc[CC];
    q[tid] = qh[((size_t)head * NB + l) * HD + tid];
    __syncthreads();
    const float scale = 0.08838834764831845f;
    if (tid < CC) {
        const float* kr = kh + (head * CC + tid) * HD;
        float s = 0.f;
        for (int d = 0; d < HD; d++) s += q[d] * kr[d];
        sc[tid] = s * scale;
    }
    __syncthreads();
    float m = -1e30f;
#pragma unroll
    for (int k = 0; k < CC; k++) m = fmaxf(m, sc[k]);
    float sum = 0.f, o = 0.f;
#pragma unroll
    for (int k = 0; k < CC; k++) {
        const float e = expf(sc[k] - m);
        sum += e;
        o += e * vh[(head * CC + k) * HD + tid];
    }
    Sp[(size_t)l * HH + head * HD + tid] = o / sum;
}

// ---------------------------------------------------------------------------
// alpha = sigmoid(S . W_gate + b_gate); Smix = alpha*Sp + (1-alpha)*S
// ---------------------------------------------------------------------------
__global__ void gate_mix_kernel(const float* __restrict__ S,
                                const float* __restrict__ Sp,
                                const float* __restrict__ Wg,
                                const float* __restrict__ bg,
                                float* __restrict__ Smix)
{
    __shared__ float red[256];
    const int l = blockIdx.x, d = threadIdx.x;
    const float sv = S[(size_t)l * HH + d];
    red[d] = sv * Wg[d];
    __syncthreads();
    for (int s = 128; s > 0; s >>= 1) {
        if (d < s) red[d] += red[d + s];
        __syncthreads();
    }
    const float alpha = 1.f / (1.f + expf(-(red[0] + bg[0])));
    Smix[(size_t)l * HH + d] = alpha * Sp[(size_t)l * HH + d] + (1.f - alpha) * sv;
}

__global__ void relu_add_kernel(const float* __restrict__ mlp,
                                float* __restrict__ Smix)
{
    const int idx = blockIdx.x * blockDim.x + threadIdx.x;
    Smix[idx] += fmaxf(mlp[idx], 0.f);
}

__global__ void rowdot_kernel(const float* __restrict__ S,
                              const float* __restrict__ W2,
                              const float* __restrict__ b2,
                              float* __restrict__ y)
{
    __shared__ float red[256];
    const int l = blockIdx.x, tid = threadIdx.x;
    red[tid] = S[(size_t)l * HH + tid] * W2[tid];
    __syncthreads();
    for (int s = 128; s > 0; s >>= 1) {
        if (tid < s) red[tid] += red[tid + s];
        __syncthreads();
    }
    if (tid == 0) y[l] = red[0] + b2[0];
}

__global__ void normalize_kernel(const float* __restrict__ y,
                                 float* __restrict__ out)
{
    __shared__ float red[1024];
    const int tid = threadIdx.x;
    const float a = y[tid], b = y[tid + 1024];
    red[tid] = a + b; __syncthreads();
    for (int s = 512; s > 0; s >>= 1) {
        if (tid < s) red[tid] += red[tid + s];
        __syncthreads();
    }
    const float mean = red[0] * (1.f / 2048.f);
    __syncthreads();
    const float da = a - mean, db = b - mean;
    red[tid] = da * da + db * db; __syncthreads();
    for (int s = 512; s > 0; s >>= 1) {
        if (tid < s) red[tid] += red[tid + s];
        __syncthreads();
    }
    const float inv = 1.f / (sqrtf(red[0] / 2047.f) + 1e-8f);
    out[tid] = da * inv;
    out[tid + 1024] = db * inv;
}

// ---------------------------------------------------------------------------
// Host driver — all launches on the default stream, graph-capturable.
// ---------------------------------------------------------------------------
extern "C" void kernel_launch(void* const* d_in, const int* in_sizes, int n_in,
                              void* d_out, int out_size)
{
    const float* x      = (const float*)d_in[0];
    const float* W_ih0  = (const float*)d_in[1];
    const float* W_hh0  = (const float*)d_in[2];
    const float* b_ih0  = (const float*)d_in[3];
    const float* b_hh0  = (const float*)d_in[4];
    const float* W_ih1  = (const float*)d_in[5];
    const float* W_hh1  = (const float*)d_in[6];
    const float* b_ih1  = (const float*)d_in[7];
    const float* b_hh1  = (const float*)d_in[8];
    const float* Wq     = (const float*)d_in[9];
    const float* bq     = (const float*)d_in[10];
    const float* Wk     = (const float*)d_in[11];
    const float* bk     = (const float*)d_in[12];
    const float* Wv     = (const float*)d_in[13];
    const float* bv     = (const float*)d_in[14];
    const float* R      = (const float*)d_in[15];
    const float* W_gate = (const float*)d_in[16];
    const float* b_gate = (const float*)d_in[17];
    const float* W1     = (const float*)d_in[18];
    const float* b1     = (const float*)d_in[19];
    const float* W2     = (const float*)d_in[20];
    const float* b2     = (const float*)d_in[21];
    float* out = (float*)d_out;

    float *xw, *ys0, *gates, *h, *qh1, *kh1, *vh1, *Bb, *qh2, *kh2, *vh2;
    float *Sp, *Smix, *mlp, *yraw;
    cudaGetSymbolAddress((void**)&xw, g_xw);
    cudaGetSymbolAddress((void**)&ys0, g_ys0);
    cudaGetSymbolAddress((void**)&gates, g_gates);
    cudaGetSymbolAddress((void**)&h, g_h);
    cudaGetSymbolAddress((void**)&qh1, g_qh1);
    cudaGetSymbolAddress((void**)&kh1, g_kh1);
    cudaGetSymbolAddress((void**)&vh1, g_vh1);
    cudaGetSymbolAddress((void**)&Bb, g_B);
    cudaGetSymbolAddress((void**)&qh2, g_qh2);
    cudaGetSymbolAddress((void**)&kh2, g_kh2);
    cudaGetSymbolAddress((void**)&vh2, g_vh2);
    cudaGetSymbolAddress((void**)&Sp, g_Sp);
    cudaGetSymbolAddress((void**)&Smix, g_Smix);
    cudaGetSymbolAddress((void**)&mlp, g_mlp);
    cudaGetSymbolAddress((void**)&yraw, g_yraw);

    const dim3 blk2(16, 16);

    // ---- Layer 0: xW0 = x @ W_ih0^T + b_ih0  (262144 x 768, K=64) ----
    gemm_bias_kernel<<<dim3(G3 / 64, NTROWS / 64), blk2>>>(
        x, INDIM, W_ih0, b_ih0, xw, G3, NTROWS, G3, INDIM);
    cudaMemsetAsync(h, 0, (size_t)NB * HH * sizeof(float));
    for (int t = 0; t < TT; t++) {
        gemm_bias_kernel<<<dim3(G3 / 64, NB / 64), blk2>>>(
            h, HH, W_hh0, b_hh0, gates, G3, NB, G3, HH);
        gru_gate_kernel<<<NB, 256>>>(
            xw + (size_t)t * G3, (size_t)TT * G3, gates, h,
            ys0 + (size_t)t * HH, (size_t)TT * HH);
    }

    // ---- Layer 1: xW1 = ys0 @ W_ih1^T + b_ih1  (262144 x 768, K=256) ----
    gemm_bias_kernel<<<dim3(G3 / 64, NTROWS / 64), blk2>>>(
        ys0, HH, W_ih1, b_ih1, xw, G3, NTROWS, G3, HH);
    cudaMemsetAsync(h, 0, (size_t)NB * HH * sizeof(float));
    for (int t = 0; t < TT; t++) {
        gemm_bias_kernel<<<dim3(G3 / 64, NB / 64), blk2>>>(
            h, HH, W_hh1, b_hh1, gates, G3, NB, G3, HH);
        gru_gate_kernel<<<NB, 256>>>(
            xw + (size_t)t * G3, (size_t)TT * G3, gates, h, nullptr, 0);
    }
    // h now holds S = out[:, -1, :]

    // ---- Attention: B = MHA(R, S, S), S' = MHA(S, B, B) ----
    proj_kernel<<<dim3(8, 2, NHD), blk2>>>(R, CC, Wq, bq, qh1);
    proj_kernel<<<dim3(8, NB / 16, NHD), blk2>>>(h, NB, Wk, bk, kh1);
    proj_kernel<<<dim3(8, NB / 16, NHD), blk2>>>(h, NB, Wv, bv, vh1);
    attn1_kernel<<<NHD * CC, 256>>>(qh1, kh1, vh1, Bb);
    proj_kernel<<<dim3(8, NB / 16, NHD), blk2>>>(h, NB, Wq, bq, qh2);
    proj_kernel<<<dim3(8, 2, NHD), blk2>>>(Bb, CC, Wk, bk, kh2);
    proj_kernel<<<dim3(8, 2, NHD), blk2>>>(Bb, CC, Wv, bv, vh2);
    attn2_kernel<<<dim3(NB, NHD), 128>>>(qh2, kh2, vh2, Sp);

    // ---- Gate mix + MLP + output ----
    gate_mix_kernel<<<NB, 256>>>(h, Sp, W_gate, b_gate, Smix);
    gemm_bias_kernel<<<dim3(HH / 64, NB / 64), blk2>>>(
        Smix, HH, W1, b1, mlp, HH, NB, HH, HH);
    relu_add_kernel<<<(NB * HH) / 256, 256>>>(mlp, Smix);
    rowdot_kernel<<<NB, 256>>>(Smix, W2, b2, yraw);
    normalize_kernel<<<1, 1024>>>(yraw, out);
}